// round 12
// baseline (speedup 1.0000x reference)
#include <cuda_runtime.h>
#include <cstdint>

// LinearCRF: out = mean_b( logZ_b - gold_b )
// R11 base (49.4us) + split-chain ILP: each lane's 16 steps become two
// INDEPENDENT 8-step chains (A: steps 0-7, B: steps 8-15) multiplied once
// at the end -- halves the exposed FFMA dependency latency per step.
// f32x2-packed rows 0,1; scalar row 2. 256 thr/block, 4 rows, 2 warps/row.
// cp.async staging into transposed conflict-free smem; 1 code byte/step.
// Exact pow2 renorm; shuffle-tree combine; single launch w/ ticket reduce.
// Runtime-guarded fast path for reference transitions; generic fallback.

#define B_DIM   8192
#define L_DIM   1024
#define RPB     4
#define THREADS 256
#define NBLOCKS (B_DIM / RPB)      // 2048
#define LN2F 0.69314718055994530942f
#define AF 2.71828182845904523536f     // e^1
#define BF 0.00673794699908546710f     // e^-5

#define EM_F4_PER_ROW 768
#define SMEM_BYTES (RPB * EM_F4_PER_ROW * 16 + RPB * 256 * 4)

__device__ float g_partials[NBLOCKS];
__device__ int   g_count = 0;

__device__ __forceinline__ void cp16(uint32_t saddr, const void* gaddr) {
    asm volatile("cp.async.cg.shared.global [%0], [%1], 16;" :: "r"(saddr), "l"(gaddr));
}

// ---- packed f32x2 helpers (Blackwell) ----
#define PACK2(out, lo, hi) \
    asm("mov.b64 %0, {%1, %2};" : "=l"(out) : "f"(lo), "f"(hi))
#define UNPACK2(lo, hi, in) \
    asm("mov.b64 {%0, %1}, %2;" : "=f"(lo), "=f"(hi) : "l"(in))
#define ADD2(d, a, b) \
    asm("add.rn.f32x2 %0, %1, %2;" : "=l"(d) : "l"(a), "l"(b))
#define MUL2(d, a, b) \
    asm("mul.rn.f32x2 %0, %1, %2;" : "=l"(d) : "l"(a), "l"(b))
#define FMA2(d, a, b, c) \
    asm("fma.rn.f32x2 %0, %1, %2, %3;" : "=l"(d) : "l"(a), "l"(b), "l"(c))

typedef unsigned long long u64t;

// ---------- FAST path step, parameterized chain state ----------
// State: PP0..PP2 = packed (row0_j,row1_j); RM0..RM2 = row 2 scalars.
#define STEP_FU(PP0, PP1, PP2, RM0, RM1, RM2, PT, GD, e0v, e1v, e2v, cbv) do { \
    float w0 = __expf(e0v), w1 = __expf(e1v), w2 = __expf(e2v);             \
    u64t sp_, t0_, t1_, n0_, n1_, n2_, w0p_, w1p_, w2p_;                    \
    ADD2(sp_, PP0, PP2);                                                    \
    FMA2(t0_, BF2, PP2, PP0); FMA2(n0_, AF2, PP1, t0_);                     \
    FMA2(n1_, AF2, sp_, PP1);                                               \
    FMA2(t1_, AF2, PP1, PP2); FMA2(n2_, BF2, PP0, t1_);                     \
    float s2_ = RM0 + RM2;                                                  \
    float R0_ = fmaf(AF, RM1, fmaf(BF, RM2, RM0));                          \
    float R1_ = fmaf(AF, s2_, RM1);                                         \
    float R2_ = fmaf(BF, RM0, fmaf(AF, RM1, RM2));                          \
    PACK2(w0p_, w0, w0); PACK2(w1p_, w1, w1); PACK2(w2p_, w2, w2);          \
    MUL2(PP0, n0_, w0p_); MUL2(PP1, n1_, w1p_); MUL2(PP2, n2_, w2p_);       \
    RM0 = R0_ * w0; RM1 = R1_ * w1; RM2 = R2_ * w2;                         \
    int tgl = (int)((cbv) & 3u);                                            \
    float etg = (tgl == 0) ? (e0v) : ((tgl == 1) ? (e1v) : (e2v));          \
    float tr  = (PT == tgl) ? 0.f : ((PT + tgl == 2) ? -5.f : 1.f);         \
    GD += tr + etg;                                                         \
    PT = tgl;                                                               \
} while (0)

#define STEP_FM(PP0, PP1, PP2, RM0, RM1, RM2, PT, GD, e0v, e1v, e2v, cbv) do { \
    unsigned cb_ = (cbv) & 0xffu;                                           \
    float w0 = __expf(e0v), w1 = __expf(e1v), w2 = __expf(e2v);             \
    u64t sp_, t0_, t1_, n0_, n1_, n2_, w0p_, w1p_, w2p_;                    \
    ADD2(sp_, PP0, PP2);                                                    \
    FMA2(t0_, BF2, PP2, PP0); FMA2(n0_, AF2, PP1, t0_);                     \
    FMA2(n1_, AF2, sp_, PP1);                                               \
    FMA2(t1_, AF2, PP1, PP2); FMA2(n2_, BF2, PP0, t1_);                     \
    float s2_ = RM0 + RM2;                                                  \
    float R0_ = fmaf(AF, RM1, fmaf(BF, RM2, RM0));                          \
    float R1_ = fmaf(AF, s2_, RM1);                                         \
    float R2_ = fmaf(BF, RM0, fmaf(AF, RM1, RM2));                          \
    PACK2(w0p_, w0, w0); PACK2(w1p_, w1, w1); PACK2(w2p_, w2, w2);          \
    MUL2(n0_, n0_, w0p_); MUL2(n1_, n1_, w1p_); MUL2(n2_, n2_, w2p_);       \
    bool u = (cb_ & 4u) != 0u;                                              \
    PP0 = u ? n0_ : PP0; PP1 = u ? n1_ : PP1; PP2 = u ? n2_ : PP2;          \
    RM0 = u ? R0_ * w0 : RM0; RM1 = u ? R1_ * w1 : RM1;                     \
    RM2 = u ? R2_ * w2 : RM2;                                               \
    int tgl = (int)(cb_ & 3u);                                              \
    float etg = (tgl == 0) ? (e0v) : ((tgl == 1) ? (e1v) : (e2v));          \
    float tr  = (PT == tgl) ? 0.f : ((PT + tgl == 2) ? -5.f : 1.f);         \
    GD += u ? (tr + etg) : 0.f;                                             \
    PT = tgl;                                                               \
} while (0)

#define GROUP_F(PP0, PP1, PP2, RM0, RM1, RM2, PT, GD, Ea, Eb, Ec, CW) do {  \
    if (((CW) & 0x04040404u) == 0x04040404u) {                              \
        STEP_FU(PP0,PP1,PP2,RM0,RM1,RM2,PT,GD, Ea.x, Ea.y, Ea.z, (CW));     \
        STEP_FU(PP0,PP1,PP2,RM0,RM1,RM2,PT,GD, Ea.w, Eb.x, Eb.y, (CW) >> 8);\
        STEP_FU(PP0,PP1,PP2,RM0,RM1,RM2,PT,GD, Eb.z, Eb.w, Ec.x, (CW) >> 16);\
        STEP_FU(PP0,PP1,PP2,RM0,RM1,RM2,PT,GD, Ec.y, Ec.z, Ec.w, (CW) >> 24);\
    } else {                                                                \
        STEP_FM(PP0,PP1,PP2,RM0,RM1,RM2,PT,GD, Ea.x, Ea.y, Ea.z, (CW));     \
        STEP_FM(PP0,PP1,PP2,RM0,RM1,RM2,PT,GD, Ea.w, Eb.x, Eb.y, (CW) >> 8);\
        STEP_FM(PP0,PP1,PP2,RM0,RM1,RM2,PT,GD, Eb.z, Eb.w, Ec.x, (CW) >> 16);\
        STEP_FM(PP0,PP1,PP2,RM0,RM1,RM2,PT,GD, Ec.y, Ec.z, Ec.w, (CW) >> 24);\
    }                                                                       \
} while (0)

// packed renorm of one chain (exact pow2 scale)
#define RENORM_PX(PP0, PP1, PP2, RM0, RM1, RM2, ES) do {                    \
    float a0_, a1_, b0_, b1_, c0_, c1_;                                     \
    UNPACK2(a0_, a1_, PP0); UNPACK2(b0_, b1_, PP1); UNPACK2(c0_, c1_, PP2); \
    float mxa = fmaxf(fmaxf(a0_, b0_), c0_);                                \
    float mxb = fmaxf(fmaxf(a1_, b1_), c1_);                                \
    float mxc = fmaxf(fmaxf(RM0, RM1), RM2);                                \
    float mx  = fmaxf(fmaxf(mxa, mxb), mxc);                                \
    int ex = (__float_as_int(mx) >> 23) - 127;                              \
    float sc = __int_as_float((127 - ex) << 23);                            \
    u64t scp_; PACK2(scp_, sc, sc);                                         \
    MUL2(PP0, PP0, scp_); MUL2(PP1, PP1, scp_); MUL2(PP2, PP2, scp_);       \
    RM0 *= sc; RM1 *= sc; RM2 *= sc;                                        \
    ES += ex;                                                               \
} while (0)

// ---------- generic fallback (scalar, unchanged semantics) ----------
#define STEP_GEN(e0v, e1v, e2v, cbv) do {                                   \
    unsigned cb_ = (cbv) & 0xffu;                                           \
    float w0 = __expf(e0v), w1 = __expf(e1v), w2 = __expf(e2v);             \
    float F00 = E00 * w0, F01 = E01 * w1, F02 = E02 * w2;                   \
    float F10 = E10 * w0, F11 = E11 * w1, F12 = E12 * w2;                   \
    float F20 = E20 * w0, F21 = E21 * w1, F22 = E22 * w2;                   \
    float n00 = fmaf(M02, F20, fmaf(M01, F10, M00 * F00));                  \
    float n01 = fmaf(M02, F21, fmaf(M01, F11, M00 * F01));                  \
    float n02 = fmaf(M02, F22, fmaf(M01, F12, M00 * F02));                  \
    float n10 = fmaf(M12, F20, fmaf(M11, F10, M10 * F00));                  \
    float n11 = fmaf(M12, F21, fmaf(M11, F11, M10 * F01));                  \
    float n12 = fmaf(M12, F22, fmaf(M11, F12, M10 * F02));                  \
    float n20 = fmaf(M22, F20, fmaf(M21, F10, M20 * F00));                  \
    float n21 = fmaf(M22, F21, fmaf(M21, F11, M20 * F01));                  \
    float n22 = fmaf(M22, F22, fmaf(M21, F12, M20 * F02));                  \
    bool u = cb_ >= 4u;                                                     \
    M00 = u ? n00 : M00; M01 = u ? n01 : M01; M02 = u ? n02 : M02;          \
    M10 = u ? n10 : M10; M11 = u ? n11 : M11; M12 = u ? n12 : M12;          \
    M20 = u ? n20 : M20; M21 = u ? n21 : M21; M22 = u ? n22 : M22;          \
    int tgl = (int)(cb_ & 3u);                                              \
    float etg = (tgl == 0) ? (e0v) : ((tgl == 1) ? (e1v) : (e2v));          \
    float add = sT[ptag * 3 + tgl] + etg;                                   \
    gold += u ? add : 0.f;                                                  \
    ptag = tgl;                                                             \
} while (0)

#define GROUP_GEN(Ea, Eb, Ec, CW) do {                                      \
    STEP_GEN(Ea.x, Ea.y, Ea.z, (CW));                                       \
    STEP_GEN(Ea.w, Eb.x, Eb.y, (CW) >> 8);                                  \
    STEP_GEN(Eb.z, Eb.w, Ec.x, (CW) >> 16);                                 \
    STEP_GEN(Ec.y, Ec.z, Ec.w, (CW) >> 24);                                 \
} while (0)

#define RENORM_S() do {                                                     \
    float mxa = fmaxf(fmaxf(M00, M01), M02);                                \
    float mxb = fmaxf(fmaxf(M10, M11), M12);                                \
    float mxc = fmaxf(fmaxf(M20, M21), M22);                                \
    float mx  = fmaxf(fmaxf(mxa, mxb), mxc);                                \
    int ex = (__float_as_int(mx) >> 23) - 127;                              \
    float sc = __int_as_float((127 - ex) << 23);                            \
    M00 *= sc; M01 *= sc; M02 *= sc;                                        \
    M10 *= sc; M11 *= sc; M12 *= sc;                                        \
    M20 *= sc; M21 *= sc; M22 *= sc;                                        \
    esum += ex;                                                             \
} while (0)

__global__ void __launch_bounds__(THREADS, 4)
crf_main_kernel(const float* __restrict__ emissions,
                const float* __restrict__ mask,
                const float* __restrict__ transitions,
                const int*   __restrict__ tags,
                float* __restrict__ out)
{
    extern __shared__ char smem[];
    float4*   emS    = (float4*)smem;
    unsigned* codesS = (unsigned*)(smem + RPB * EM_F4_PER_ROW * 16);
    __shared__ float sT[9];
    __shared__ float sHalf[8][11];
    __shared__ float srow[RPB];
    __shared__ int   sLast;

    const int tid  = threadIdx.x;
    const int lane = tid & 31;
    const int w    = tid >> 5;      // 0..7
    const int r    = w >> 1;        // local row
    const int h    = w & 1;         // half
    const int row0 = blockIdx.x * RPB;

    if (tid < 9) sT[tid] = transitions[tid];

    uint32_t emS_a = (uint32_t)__cvta_generic_to_shared(emS);

    // ---- stage emissions: gmem-linear f4 -> smem transposed (j*64 + owner) ----
    const float4* emG = (const float4*)emissions + (size_t)row0 * 768;
    #pragma unroll
    for (int rr = 0; rr < RPB; ++rr) {
        #pragma unroll
        for (int i = 0; i < 3; ++i) {
            int k = tid + i * THREADS;              // 0..767
            int o = k / 12, j = k - o * 12;
            cp16(emS_a + (uint32_t)((rr * EM_F4_PER_ROW + j * 64 + o) << 4),
                 emG + (size_t)rr * 768 + k);
        }
    }
    asm volatile("cp.async.commit_group;");

    // ---- pack tags+mask into code bytes ----
    const int4*   tgG = (const int4*)tags + (size_t)row0 * 256;
    const float4* mkG = (const float4*)mask + (size_t)row0 * 256;
    #pragma unroll
    for (int rr = 0; rr < RPB; ++rr) {
        int4   tg = tgG[(size_t)rr * 256 + tid];
        float4 mk = mkG[(size_t)rr * 256 + tid];
        unsigned cw = ((unsigned)(tg.x & 3) | (mk.x > 0.f ? 4u : 0u))
                    | (((unsigned)(tg.y & 3) | (mk.y > 0.f ? 4u : 0u)) << 8)
                    | (((unsigned)(tg.z & 3) | (mk.z > 0.f ? 4u : 0u)) << 16)
                    | (((unsigned)(tg.w & 3) | (mk.w > 0.f ? 4u : 0u)) << 24);
        codesS[rr * 256 + tid] = cw;
    }
    asm volatile("cp.async.wait_group 0;");
    __syncthreads();

    bool fastpath = (sT[0] == 0.f && sT[1] == 1.f && sT[2] == -5.f &&
                     sT[3] == 1.f && sT[4] == 0.f && sT[5] == 1.f &&
                     sT[6] == -5.f && sT[7] == 1.f && sT[8] == 0.f);

    // ---- per-lane 16 steps ----
    const int o = h * 32 + lane;                    // owner 0..63 within row
    const float4* em = emS + r * EM_F4_PER_ROW + o; // access em[(3g+u)*64]
    int4 c4 = ((const int4*)codesS)[r * 64 + o];
    if (h == 0 && lane == 0) c4.x &= ~4;            // step 0 = init, not a transition

    unsigned prevw = __shfl_up_sync(0xffffffffu, (unsigned)c4.w, 1);
    int ptag;
    if (lane == 0) {
        ptag = (h == 0) ? (c4.x & 3)
             : (tags[(size_t)(row0 + r) * L_DIM + 511] & 3);
    } else {
        ptag = (int)((prevw >> 24) & 3u);
    }

    float M00, M01, M02, M10, M11, M12, M20, M21, M22;
    float gold = 0.f;
    int esum = 0;

    if (fastpath) {
        u64t PA0, PA1, PA2, PB0, PB1, PB2, AF2, BF2;
        float RA0, RA1, RA2, RB0, RB1, RB2;
        {
            float one = 1.f, zero = 0.f, af = AF, bf = BF;
            PACK2(PA0, one, zero); PACK2(PA1, zero, one); PACK2(PA2, zero, zero);
            PACK2(PB0, one, zero); PACK2(PB1, zero, one); PACK2(PB2, zero, zero);
            PACK2(AF2, af, af);    PACK2(BF2, bf, bf);
        }
        RA0 = 0.f; RA1 = 0.f; RA2 = 1.f;
        RB0 = 0.f; RB1 = 0.f; RB2 = 1.f;
        int ptA = ptag;
        int ptB = (int)(((unsigned)c4.y >> 24) & 3u);   // tag of step 7 (lane-local)
        float gA = 0.f, gB = 0.f;
        int esA = 0, esB = 0;

        // chain A: steps 0-7 (c4.x, c4.y); chain B: steps 8-15 (c4.z, c4.w)
        {
            float4 xa = em[0 * 64], xb = em[1 * 64], xc = em[2 * 64];
            float4 ya = em[6 * 64], yb = em[7 * 64], yc = em[8 * 64];
            GROUP_F(PA0, PA1, PA2, RA0, RA1, RA2, ptA, gA, xa, xb, xc, (unsigned)c4.x);
            GROUP_F(PB0, PB1, PB2, RB0, RB1, RB2, ptB, gB, ya, yb, yc, (unsigned)c4.z);
            xa = em[3 * 64]; xb = em[4 * 64]; xc = em[5 * 64];
            ya = em[9 * 64]; yb = em[10 * 64]; yc = em[11 * 64];
            GROUP_F(PA0, PA1, PA2, RA0, RA1, RA2, ptA, gA, xa, xb, xc, (unsigned)c4.y);
            GROUP_F(PB0, PB1, PB2, RB0, RB1, RB2, ptB, gB, ya, yb, yc, (unsigned)c4.w);
        }
        RENORM_PX(PA0, PA1, PA2, RA0, RA1, RA2, esA);
        RENORM_PX(PB0, PB1, PB2, RB0, RB1, RB2, esB);

        // lane-local combine: M = A * B (A = earlier steps)
        float A00, A10, A01, A11, A02, A12;
        float B00, B10, B01, B11, B02, B12;
        UNPACK2(A00, A10, PA0); UNPACK2(A01, A11, PA1); UNPACK2(A02, A12, PA2);
        UNPACK2(B00, B10, PB0); UNPACK2(B01, B11, PB1); UNPACK2(B02, B12, PB2);
        M00 = fmaf(A02, RB0, fmaf(A01, B10, A00 * B00));
        M01 = fmaf(A02, RB1, fmaf(A01, B11, A00 * B01));
        M02 = fmaf(A02, RB2, fmaf(A01, B12, A00 * B02));
        M10 = fmaf(A12, RB0, fmaf(A11, B10, A10 * B00));
        M11 = fmaf(A12, RB1, fmaf(A11, B11, A10 * B01));
        M12 = fmaf(A12, RB2, fmaf(A11, B12, A10 * B02));
        M20 = fmaf(RA2, RB0, fmaf(RA1, B10, RA0 * B00));
        M21 = fmaf(RA2, RB1, fmaf(RA1, B11, RA0 * B01));
        M22 = fmaf(RA2, RB2, fmaf(RA1, B12, RA0 * B02));
        gold = gA + gB;
        esum = esA + esB;
    } else {
        M00 = 1.f; M01 = 0.f; M02 = 0.f;
        M10 = 0.f; M11 = 1.f; M12 = 0.f;
        M20 = 0.f; M21 = 0.f; M22 = 1.f;
        float E00 = __expf(sT[0]), E01 = __expf(sT[1]), E02 = __expf(sT[2]);
        float E10 = __expf(sT[3]), E11 = __expf(sT[4]), E12 = __expf(sT[5]);
        float E20 = __expf(sT[6]), E21 = __expf(sT[7]), E22 = __expf(sT[8]);
        float4 eAa = em[0 * 64], eAb = em[1 * 64], eAc = em[2 * 64];
        float4 eBa = em[3 * 64], eBb = em[4 * 64], eBc = em[5 * 64];
        GROUP_GEN(eAa, eAb, eAc, (unsigned)c4.x);
        RENORM_S();
        eAa = em[6 * 64]; eAb = em[7 * 64]; eAc = em[8 * 64];
        GROUP_GEN(eBa, eBb, eBc, (unsigned)c4.y);
        RENORM_S();
        eBa = em[9 * 64]; eBb = em[10 * 64]; eBc = em[11 * 64];
        GROUP_GEN(eAa, eAb, eAc, (unsigned)c4.z);
        RENORM_S();
        GROUP_GEN(eBa, eBb, eBc, (unsigned)c4.w);
        RENORM_S();
    }

    // ---- in-warp ordered tree product over the 32 lane chunks ----
    float e = (float)esum;
    #pragma unroll
    for (int s = 1; s < 32; s <<= 1) {
        float Q00 = __shfl_down_sync(0xffffffffu, M00, s);
        float Q01 = __shfl_down_sync(0xffffffffu, M01, s);
        float Q02 = __shfl_down_sync(0xffffffffu, M02, s);
        float Q10 = __shfl_down_sync(0xffffffffu, M10, s);
        float Q11 = __shfl_down_sync(0xffffffffu, M11, s);
        float Q12 = __shfl_down_sync(0xffffffffu, M12, s);
        float Q20 = __shfl_down_sync(0xffffffffu, M20, s);
        float Q21 = __shfl_down_sync(0xffffffffu, M21, s);
        float Q22 = __shfl_down_sync(0xffffffffu, M22, s);
        float eq  = __shfl_down_sync(0xffffffffu, e,   s);
        float gq  = __shfl_down_sync(0xffffffffu, gold, s);

        float q00 = fmaf(M02, Q20, fmaf(M01, Q10, M00 * Q00));
        float q01 = fmaf(M02, Q21, fmaf(M01, Q11, M00 * Q01));
        float q02 = fmaf(M02, Q22, fmaf(M01, Q12, M00 * Q02));
        float q10 = fmaf(M12, Q20, fmaf(M11, Q10, M10 * Q00));
        float q11 = fmaf(M12, Q21, fmaf(M11, Q11, M10 * Q01));
        float q12 = fmaf(M12, Q22, fmaf(M11, Q12, M10 * Q02));
        float q20 = fmaf(M22, Q20, fmaf(M21, Q10, M20 * Q00));
        float q21 = fmaf(M22, Q21, fmaf(M21, Q11, M20 * Q01));
        float q22 = fmaf(M22, Q22, fmaf(M21, Q12, M20 * Q02));

        float mxa = fmaxf(fmaxf(q00, q01), q02);
        float mxb = fmaxf(fmaxf(q10, q11), q12);
        float mxc = fmaxf(fmaxf(q20, q21), q22);
        float mx  = fmaxf(fmaxf(mxa, mxb), mxc);
        int ex = (__float_as_int(mx) >> 23) - 127;
        float sc = __int_as_float((127 - ex) << 23);
        M00 = q00 * sc; M01 = q01 * sc; M02 = q02 * sc;
        M10 = q10 * sc; M11 = q11 * sc; M12 = q12 * sc;
        M20 = q20 * sc; M21 = q21 * sc; M22 = q22 * sc;

        e += eq + (float)ex;
        gold += gq;
    }

    if (lane == 0) {
        float* dst = sHalf[w];
        dst[0] = M00; dst[1] = M01; dst[2] = M02;
        dst[3] = M10; dst[4] = M11; dst[5] = M12;
        dst[6] = M20; dst[7] = M21; dst[8] = M22;
        dst[9] = e;   dst[10] = gold;
    }
    __syncthreads();

    // ---- per-row: alpha0 * H0 * H1, logZ, gold base term ----
    if (tid < RPB) {
        int rr = tid;
        const float* A  = sHalf[rr * 2];
        const float* Bm = sHalf[rr * 2 + 1];

        float4 e0 = emS[rr * EM_F4_PER_ROW];      // em[row][0][0..2]
        float a0 = __expf(e0.x), a1 = __expf(e0.y), a2 = __expf(e0.z);
        float u0 = fmaf(a2, A[6], fmaf(a1, A[3], a0 * A[0]));
        float u1 = fmaf(a2, A[7], fmaf(a1, A[4], a0 * A[1]));
        float u2 = fmaf(a2, A[8], fmaf(a1, A[5], a0 * A[2]));
        float v0 = fmaf(u2, Bm[6], fmaf(u1, Bm[3], u0 * Bm[0]));
        float v1 = fmaf(u2, Bm[7], fmaf(u1, Bm[4], u0 * Bm[1]));
        float v2 = fmaf(u2, Bm[8], fmaf(u1, Bm[5], u0 * Bm[2]));

        float esumT = A[9] + Bm[9];
        float goldT = A[10] + Bm[10];

        unsigned c0 = codesS[rr * 256];
        int   t0 = (int)(c0 & 3u);
        float m0 = (float)((c0 >> 2) & 1u);
        float em0t = (t0 == 0) ? e0.x : ((t0 == 1) ? e0.y : e0.z);
        goldT += m0 * em0t;

        float logZ = __logf(v0 + v1 + v2) + esumT * LN2F;
        srow[rr] = logZ - goldT;
    }
    __syncthreads();

    if (tid == 0) {
        g_partials[blockIdx.x] = (srow[0] + srow[1]) + (srow[2] + srow[3]);
        __threadfence();
        int tk = atomicAdd(&g_count, 1);
        sLast = (tk == NBLOCKS - 1);
    }
    __syncthreads();

    // ---- last block: fixed-order final reduction ----
    if (sLast) {
        float s = 0.f;
        #pragma unroll
        for (int i = 0; i < NBLOCKS / THREADS; ++i)
            s += __ldcg(&g_partials[tid * (NBLOCKS / THREADS) + i]);
        float* red = (float*)smem;                // reuse staging smem
        red[tid] = s;
        __syncthreads();
        #pragma unroll
        for (int st = THREADS / 2; st > 0; st >>= 1) {
            if (tid < st) red[tid] += red[tid + st];
            __syncthreads();
        }
        if (tid == 0) {
            out[0] = red[0] * (1.0f / (float)B_DIM);
            g_count = 0;                          // reset for next graph replay
        }
    }
}

extern "C" void kernel_launch(void* const* d_in, const int* in_sizes, int n_in,
                              void* d_out, int out_size)
{
    const float* emissions   = (const float*)d_in[0];
    const float* mask        = (const float*)d_in[1];
    const float* transitions = (const float*)d_in[2];
    const int*   tags        = (const int*)d_in[3];
    float* out = (float*)d_out;

    cudaFuncSetAttribute(crf_main_kernel,
                         cudaFuncAttributeMaxDynamicSharedMemorySize, SMEM_BYTES);
    crf_main_kernel<<<NBLOCKS, THREADS, SMEM_BYTES>>>(emissions, mask, transitions,
                                                      tags, out);
}

// round 13
// speedup vs baseline: 1.0437x; 1.0437x over previous
#include <cuda_runtime.h>
#include <cstdint>

// LinearCRF: out = mean_b( logZ_b - gold_b )
// R11 base (49.4us best) + diet: tree renorm only at rounds s=2,8;
// identity-specialized first step in the unconditional fast branch.
// f32x2-packed rows 0,1 (FFMA2); scalar row 2. 256 thr/block, 4 rows,
// 2 warps/row, lane = 16 steps. cp.async staging into transposed
// conflict-free smem; tags+mask packed to 1 byte/step. Exact pow2 renorm
// every 8 steps; shuffle-tree combine; single launch w/ ticket reduce.
// Runtime-guarded fast path for reference transitions; generic fallback.

#define B_DIM   8192
#define L_DIM   1024
#define RPB     4
#define THREADS 256
#define NBLOCKS (B_DIM / RPB)      // 2048
#define LN2F 0.69314718055994530942f
#define AF 2.71828182845904523536f     // e^1
#define BF 0.00673794699908546710f     // e^-5

#define EM_F4_PER_ROW 768
#define SMEM_BYTES (RPB * EM_F4_PER_ROW * 16 + RPB * 256 * 4)

__device__ float g_partials[NBLOCKS];
__device__ int   g_count = 0;

__device__ __forceinline__ void cp16(uint32_t saddr, const void* gaddr) {
    asm volatile("cp.async.cg.shared.global [%0], [%1], 16;" :: "r"(saddr), "l"(gaddr));
}

// ---- packed f32x2 helpers (Blackwell) ----
#define PACK2(out, lo, hi) \
    asm("mov.b64 %0, {%1, %2};" : "=l"(out) : "f"(lo), "f"(hi))
#define UNPACK2(lo, hi, in) \
    asm("mov.b64 {%0, %1}, %2;" : "=f"(lo), "=f"(hi) : "l"(in))
#define ADD2(d, a, b) \
    asm("add.rn.f32x2 %0, %1, %2;" : "=l"(d) : "l"(a), "l"(b))
#define MUL2(d, a, b) \
    asm("mul.rn.f32x2 %0, %1, %2;" : "=l"(d) : "l"(a), "l"(b))
#define FMA2(d, a, b, c) \
    asm("fma.rn.f32x2 %0, %1, %2, %3;" : "=l"(d) : "l"(a), "l"(b), "l"(c))

typedef unsigned long long u64t;

// ---------- FAST path: E = [[1,a,b],[a,1,a],[b,a,1]], T in {0,1,-5} ----------
// State: P0,P1,P2 = packed (row0_j,row1_j) per column j; M20..M22 = row 2.
#define STEP_FAST_U(e0v, e1v, e2v, cbv) do {                                \
    float w0 = __expf(e0v), w1 = __expf(e1v), w2 = __expf(e2v);             \
    u64t sp_, t0_, t1_, n0_, n1_, n2_, w0p_, w1p_, w2p_;                    \
    ADD2(sp_, P0, P2);                                                      \
    FMA2(t0_, BF2, P2, P0); FMA2(n0_, AF2, P1, t0_);                        \
    FMA2(n1_, AF2, sp_, P1);                                                \
    FMA2(t1_, AF2, P1, P2); FMA2(n2_, BF2, P0, t1_);                        \
    float s2_ = M20 + M22;                                                  \
    float R0_ = fmaf(AF, M21, fmaf(BF, M22, M20));                          \
    float R1_ = fmaf(AF, s2_, M21);                                         \
    float R2_ = fmaf(BF, M20, fmaf(AF, M21, M22));                          \
    PACK2(w0p_, w0, w0); PACK2(w1p_, w1, w1); PACK2(w2p_, w2, w2);          \
    MUL2(P0, n0_, w0p_); MUL2(P1, n1_, w1p_); MUL2(P2, n2_, w2p_);          \
    M20 = R0_ * w0; M21 = R1_ * w1; M22 = R2_ * w2;                         \
    int tgl = (int)((cbv) & 3u);                                            \
    float etg = (tgl == 0) ? (e0v) : ((tgl == 1) ? (e1v) : (e2v));          \
    float tr  = (ptag == tgl) ? 0.f : ((ptag + tgl == 2) ? -5.f : 1.f);     \
    gold += tr + etg;                                                       \
    ptag = tgl;                                                             \
} while (0)

// First step from identity: M = E * diag(w) written directly.
#define STEP_FAST_I(e0v, e1v, e2v, cbv) do {                                \
    float w0 = __expf(e0v), w1 = __expf(e1v), w2 = __expf(e2v);             \
    float aw0 = AF * w0, aw1 = AF * w1, aw2 = AF * w2;                      \
    PACK2(P0, w0, aw0);                                                     \
    PACK2(P1, aw1, w1);                                                     \
    float bw2 = BF * w2;                                                    \
    PACK2(P2, bw2, aw2);                                                    \
    M20 = BF * w0; M21 = aw1; M22 = w2;                                     \
    int tgl = (int)((cbv) & 3u);                                            \
    float etg = (tgl == 0) ? (e0v) : ((tgl == 1) ? (e1v) : (e2v));          \
    float tr  = (ptag == tgl) ? 0.f : ((ptag + tgl == 2) ? -5.f : 1.f);     \
    gold += tr + etg;                                                       \
    ptag = tgl;                                                             \
} while (0)

#define STEP_FAST_M(e0v, e1v, e2v, cbv) do {                                \
    unsigned cb_ = (cbv) & 0xffu;                                           \
    float w0 = __expf(e0v), w1 = __expf(e1v), w2 = __expf(e2v);             \
    u64t sp_, t0_, t1_, n0_, n1_, n2_, w0p_, w1p_, w2p_;                    \
    ADD2(sp_, P0, P2);                                                      \
    FMA2(t0_, BF2, P2, P0); FMA2(n0_, AF2, P1, t0_);                        \
    FMA2(n1_, AF2, sp_, P1);                                                \
    FMA2(t1_, AF2, P1, P2); FMA2(n2_, BF2, P0, t1_);                        \
    float s2_ = M20 + M22;                                                  \
    float R0_ = fmaf(AF, M21, fmaf(BF, M22, M20));                          \
    float R1_ = fmaf(AF, s2_, M21);                                         \
    float R2_ = fmaf(BF, M20, fmaf(AF, M21, M22));                          \
    PACK2(w0p_, w0, w0); PACK2(w1p_, w1, w1); PACK2(w2p_, w2, w2);          \
    MUL2(n0_, n0_, w0p_); MUL2(n1_, n1_, w1p_); MUL2(n2_, n2_, w2p_);       \
    bool u = (cb_ & 4u) != 0u;                                              \
    P0 = u ? n0_ : P0; P1 = u ? n1_ : P1; P2 = u ? n2_ : P2;                \
    M20 = u ? R0_ * w0 : M20; M21 = u ? R1_ * w1 : M21;                     \
    M22 = u ? R2_ * w2 : M22;                                               \
    int tgl = (int)(cb_ & 3u);                                              \
    float etg = (tgl == 0) ? (e0v) : ((tgl == 1) ? (e1v) : (e2v));          \
    float tr  = (ptag == tgl) ? 0.f : ((ptag + tgl == 2) ? -5.f : 1.f);     \
    gold += u ? (tr + etg) : 0.f;                                           \
    ptag = tgl;                                                             \
} while (0)

// first group of a lane: identity-specialized first step on the fast branch
#define GROUP_FAST0(Ea, Eb, Ec, CW) do {                                    \
    if (((CW) & 0x04040404u) == 0x04040404u) {                              \
        STEP_FAST_I(Ea.x, Ea.y, Ea.z, (CW));                                \
        STEP_FAST_U(Ea.w, Eb.x, Eb.y, (CW) >> 8);                           \
        STEP_FAST_U(Eb.z, Eb.w, Ec.x, (CW) >> 16);                          \
        STEP_FAST_U(Ec.y, Ec.z, Ec.w, (CW) >> 24);                          \
    } else {                                                                \
        STEP_FAST_M(Ea.x, Ea.y, Ea.z, (CW));                                \
        STEP_FAST_M(Ea.w, Eb.x, Eb.y, (CW) >> 8);                           \
        STEP_FAST_M(Eb.z, Eb.w, Ec.x, (CW) >> 16);                          \
        STEP_FAST_M(Ec.y, Ec.z, Ec.w, (CW) >> 24);                          \
    }                                                                       \
} while (0)

#define GROUP_FAST(Ea, Eb, Ec, CW) do {                                     \
    if (((CW) & 0x04040404u) == 0x04040404u) {                              \
        STEP_FAST_U(Ea.x, Ea.y, Ea.z, (CW));                                \
        STEP_FAST_U(Ea.w, Eb.x, Eb.y, (CW) >> 8);                           \
        STEP_FAST_U(Eb.z, Eb.w, Ec.x, (CW) >> 16);                          \
        STEP_FAST_U(Ec.y, Ec.z, Ec.w, (CW) >> 24);                          \
    } else {                                                                \
        STEP_FAST_M(Ea.x, Ea.y, Ea.z, (CW));                                \
        STEP_FAST_M(Ea.w, Eb.x, Eb.y, (CW) >> 8);                           \
        STEP_FAST_M(Eb.z, Eb.w, Ec.x, (CW) >> 16);                          \
        STEP_FAST_M(Ec.y, Ec.z, Ec.w, (CW) >> 24);                          \
    }                                                                       \
} while (0)

// packed renorm: exact pow2 scale of all 9 entries
#define RENORM_P() do {                                                     \
    float a0_, a1_, b0_, b1_, c0_, c1_;                                     \
    UNPACK2(a0_, a1_, P0); UNPACK2(b0_, b1_, P1); UNPACK2(c0_, c1_, P2);    \
    float mxa = fmaxf(fmaxf(a0_, b0_), c0_);                                \
    float mxb = fmaxf(fmaxf(a1_, b1_), c1_);                                \
    float mxc = fmaxf(fmaxf(M20, M21), M22);                                \
    float mx  = fmaxf(fmaxf(mxa, mxb), mxc);                                \
    int ex = (__float_as_int(mx) >> 23) - 127;                              \
    float sc = __int_as_float((127 - ex) << 23);                            \
    u64t scp_; PACK2(scp_, sc, sc);                                         \
    MUL2(P0, P0, scp_); MUL2(P1, P1, scp_); MUL2(P2, P2, scp_);             \
    M20 *= sc; M21 *= sc; M22 *= sc;                                        \
    esum += ex;                                                             \
} while (0)

// ---------- generic fallback (scalar, unchanged semantics) ----------
#define STEP_GEN(e0v, e1v, e2v, cbv) do {                                   \
    unsigned cb_ = (cbv) & 0xffu;                                           \
    float w0 = __expf(e0v), w1 = __expf(e1v), w2 = __expf(e2v);             \
    float F00 = E00 * w0, F01 = E01 * w1, F02 = E02 * w2;                   \
    float F10 = E10 * w0, F11 = E11 * w1, F12 = E12 * w2;                   \
    float F20 = E20 * w0, F21 = E21 * w1, F22 = E22 * w2;                   \
    float n00 = fmaf(M02, F20, fmaf(M01, F10, M00 * F00));                  \
    float n01 = fmaf(M02, F21, fmaf(M01, F11, M00 * F01));                  \
    float n02 = fmaf(M02, F22, fmaf(M01, F12, M00 * F02));                  \
    float n10 = fmaf(M12, F20, fmaf(M11, F10, M10 * F00));                  \
    float n11 = fmaf(M12, F21, fmaf(M11, F11, M10 * F01));                  \
    float n12 = fmaf(M12, F22, fmaf(M11, F12, M10 * F02));                  \
    float n20 = fmaf(M22, F20, fmaf(M21, F10, M20 * F00));                  \
    float n21 = fmaf(M22, F21, fmaf(M21, F11, M20 * F01));                  \
    float n22 = fmaf(M22, F22, fmaf(M21, F12, M20 * F02));                  \
    bool u = cb_ >= 4u;                                                     \
    M00 = u ? n00 : M00; M01 = u ? n01 : M01; M02 = u ? n02 : M02;          \
    M10 = u ? n10 : M10; M11 = u ? n11 : M11; M12 = u ? n12 : M12;          \
    M20 = u ? n20 : M20; M21 = u ? n21 : M21; M22 = u ? n22 : M22;          \
    int tgl = (int)(cb_ & 3u);                                              \
    float etg = (tgl == 0) ? (e0v) : ((tgl == 1) ? (e1v) : (e2v));          \
    float add = sT[ptag * 3 + tgl] + etg;                                   \
    gold += u ? add : 0.f;                                                  \
    ptag = tgl;                                                             \
} while (0)

#define GROUP_GEN(Ea, Eb, Ec, CW) do {                                      \
    STEP_GEN(Ea.x, Ea.y, Ea.z, (CW));                                       \
    STEP_GEN(Ea.w, Eb.x, Eb.y, (CW) >> 8);                                  \
    STEP_GEN(Eb.z, Eb.w, Ec.x, (CW) >> 16);                                 \
    STEP_GEN(Ec.y, Ec.z, Ec.w, (CW) >> 24);                                 \
} while (0)

#define RENORM_S() do {                                                     \
    float mxa = fmaxf(fmaxf(M00, M01), M02);                                \
    float mxb = fmaxf(fmaxf(M10, M11), M12);                                \
    float mxc = fmaxf(fmaxf(M20, M21), M22);                                \
    float mx  = fmaxf(fmaxf(mxa, mxb), mxc);                                \
    int ex = (__float_as_int(mx) >> 23) - 127;                              \
    float sc = __int_as_float((127 - ex) << 23);                            \
    M00 *= sc; M01 *= sc; M02 *= sc;                                        \
    M10 *= sc; M11 *= sc; M12 *= sc;                                        \
    M20 *= sc; M21 *= sc; M22 *= sc;                                        \
    esum += ex;                                                             \
} while (0)

__global__ void __launch_bounds__(THREADS, 4)
crf_main_kernel(const float* __restrict__ emissions,
                const float* __restrict__ mask,
                const float* __restrict__ transitions,
                const int*   __restrict__ tags,
                float* __restrict__ out)
{
    extern __shared__ char smem[];
    float4*   emS    = (float4*)smem;
    unsigned* codesS = (unsigned*)(smem + RPB * EM_F4_PER_ROW * 16);
    __shared__ float sT[9];
    __shared__ float sHalf[8][11];
    __shared__ float srow[RPB];
    __shared__ int   sLast;

    const int tid  = threadIdx.x;
    const int lane = tid & 31;
    const int w    = tid >> 5;      // 0..7
    const int r    = w >> 1;        // local row
    const int h    = w & 1;         // half
    const int row0 = blockIdx.x * RPB;

    if (tid < 9) sT[tid] = transitions[tid];

    uint32_t emS_a = (uint32_t)__cvta_generic_to_shared(emS);

    // ---- stage emissions: gmem-linear f4 -> smem transposed (j*64 + owner) ----
    const float4* emG = (const float4*)emissions + (size_t)row0 * 768;
    #pragma unroll
    for (int rr = 0; rr < RPB; ++rr) {
        #pragma unroll
        for (int i = 0; i < 3; ++i) {
            int k = tid + i * THREADS;              // 0..767
            int o = k / 12, j = k - o * 12;
            cp16(emS_a + (uint32_t)((rr * EM_F4_PER_ROW + j * 64 + o) << 4),
                 emG + (size_t)rr * 768 + k);
        }
    }
    asm volatile("cp.async.commit_group;");

    // ---- pack tags+mask into code bytes ----
    const int4*   tgG = (const int4*)tags + (size_t)row0 * 256;
    const float4* mkG = (const float4*)mask + (size_t)row0 * 256;
    #pragma unroll
    for (int rr = 0; rr < RPB; ++rr) {
        int4   tg = tgG[(size_t)rr * 256 + tid];
        float4 mk = mkG[(size_t)rr * 256 + tid];
        unsigned cw = ((unsigned)(tg.x & 3) | (mk.x > 0.f ? 4u : 0u))
                    | (((unsigned)(tg.y & 3) | (mk.y > 0.f ? 4u : 0u)) << 8)
                    | (((unsigned)(tg.z & 3) | (mk.z > 0.f ? 4u : 0u)) << 16)
                    | (((unsigned)(tg.w & 3) | (mk.w > 0.f ? 4u : 0u)) << 24);
        codesS[rr * 256 + tid] = cw;
    }
    asm volatile("cp.async.wait_group 0;");
    __syncthreads();

    bool fastpath = (sT[0] == 0.f && sT[1] == 1.f && sT[2] == -5.f &&
                     sT[3] == 1.f && sT[4] == 0.f && sT[5] == 1.f &&
                     sT[6] == -5.f && sT[7] == 1.f && sT[8] == 0.f);

    // ---- per-lane 16 steps ----
    const int o = h * 32 + lane;                    // owner 0..63 within row
    const float4* em = emS + r * EM_F4_PER_ROW + o; // access em[(3g+u)*64]
    int4 c4 = ((const int4*)codesS)[r * 64 + o];
    if (h == 0 && lane == 0) c4.x &= ~4;            // step 0 = init, not a transition

    unsigned prevw = __shfl_up_sync(0xffffffffu, (unsigned)c4.w, 1);
    int ptag;
    if (lane == 0) {
        ptag = (h == 0) ? (c4.x & 3)
             : (tags[(size_t)(row0 + r) * L_DIM + 511] & 3);
    } else {
        ptag = (int)((prevw >> 24) & 3u);
    }

    float M00, M01, M02, M10, M11, M12;
    float M20 = 0.f, M21 = 0.f, M22 = 1.f;
    float gold = 0.f;
    int esum = 0;

    if (fastpath) {
        u64t P0, P1, P2, AF2, BF2;
        {
            float one = 1.f, zero = 0.f, af = AF, bf = BF;
            PACK2(P0, one, zero);
            PACK2(P1, zero, one);
            PACK2(P2, zero, zero);
            PACK2(AF2, af, af);
            PACK2(BF2, bf, bf);
        }
        float4 eAa = em[0 * 64], eAb = em[1 * 64], eAc = em[2 * 64];
        float4 eBa = em[3 * 64], eBb = em[4 * 64], eBc = em[5 * 64];
        GROUP_FAST0(eAa, eAb, eAc, (unsigned)c4.x);
        eAa = em[6 * 64]; eAb = em[7 * 64]; eAc = em[8 * 64];
        GROUP_FAST(eBa, eBb, eBc, (unsigned)c4.y);
        RENORM_P();
        eBa = em[9 * 64]; eBb = em[10 * 64]; eBc = em[11 * 64];
        GROUP_FAST(eAa, eAb, eAc, (unsigned)c4.z);
        GROUP_FAST(eBa, eBb, eBc, (unsigned)c4.w);
        RENORM_P();
        UNPACK2(M00, M10, P0);
        UNPACK2(M01, M11, P1);
        UNPACK2(M02, M12, P2);
    } else {
        M00 = 1.f; M01 = 0.f; M02 = 0.f;
        M10 = 0.f; M11 = 1.f; M12 = 0.f;
        float E00 = __expf(sT[0]), E01 = __expf(sT[1]), E02 = __expf(sT[2]);
        float E10 = __expf(sT[3]), E11 = __expf(sT[4]), E12 = __expf(sT[5]);
        float E20 = __expf(sT[6]), E21 = __expf(sT[7]), E22 = __expf(sT[8]);
        float4 eAa = em[0 * 64], eAb = em[1 * 64], eAc = em[2 * 64];
        float4 eBa = em[3 * 64], eBb = em[4 * 64], eBc = em[5 * 64];
        GROUP_GEN(eAa, eAb, eAc, (unsigned)c4.x);
        RENORM_S();
        eAa = em[6 * 64]; eAb = em[7 * 64]; eAc = em[8 * 64];
        GROUP_GEN(eBa, eBb, eBc, (unsigned)c4.y);
        RENORM_S();
        eBa = em[9 * 64]; eBb = em[10 * 64]; eBc = em[11 * 64];
        GROUP_GEN(eAa, eAb, eAc, (unsigned)c4.z);
        RENORM_S();
        GROUP_GEN(eBa, eBb, eBc, (unsigned)c4.w);
        RENORM_S();
    }

    // ---- in-warp ordered tree product over the 32 lane chunks ----
    // Inputs normalized (max in [1,2)); renorm only at s==2 and s==8:
    // two unrenormed rounds bound entries by 3*3*2^4 = 432 (no overflow),
    // and >= ~6e-6 (no underflow) before the next renorm.
    float e = (float)esum;
    #pragma unroll
    for (int s = 1; s < 32; s <<= 1) {
        float Q00 = __shfl_down_sync(0xffffffffu, M00, s);
        float Q01 = __shfl_down_sync(0xffffffffu, M01, s);
        float Q02 = __shfl_down_sync(0xffffffffu, M02, s);
        float Q10 = __shfl_down_sync(0xffffffffu, M10, s);
        float Q11 = __shfl_down_sync(0xffffffffu, M11, s);
        float Q12 = __shfl_down_sync(0xffffffffu, M12, s);
        float Q20 = __shfl_down_sync(0xffffffffu, M20, s);
        float Q21 = __shfl_down_sync(0xffffffffu, M21, s);
        float Q22 = __shfl_down_sync(0xffffffffu, M22, s);
        float eq  = __shfl_down_sync(0xffffffffu, e,   s);
        float gq  = __shfl_down_sync(0xffffffffu, gold, s);

        float q00 = fmaf(M02, Q20, fmaf(M01, Q10, M00 * Q00));
        float q01 = fmaf(M02, Q21, fmaf(M01, Q11, M00 * Q01));
        float q02 = fmaf(M02, Q22, fmaf(M01, Q12, M00 * Q02));
        float q10 = fmaf(M12, Q20, fmaf(M11, Q10, M10 * Q00));
        float q11 = fmaf(M12, Q21, fmaf(M11, Q11, M10 * Q01));
        float q12 = fmaf(M12, Q22, fmaf(M11, Q12, M10 * Q02));
        float q20 = fmaf(M22, Q20, fmaf(M21, Q10, M20 * Q00));
        float q21 = fmaf(M22, Q21, fmaf(M21, Q11, M20 * Q01));
        float q22 = fmaf(M22, Q22, fmaf(M21, Q12, M20 * Q02));

        if (s == 2 || s == 8) {
            float mxa = fmaxf(fmaxf(q00, q01), q02);
            float mxb = fmaxf(fmaxf(q10, q11), q12);
            float mxc = fmaxf(fmaxf(q20, q21), q22);
            float mx  = fmaxf(fmaxf(mxa, mxb), mxc);
            int ex = (__float_as_int(mx) >> 23) - 127;
            float sc = __int_as_float((127 - ex) << 23);
            M00 = q00 * sc; M01 = q01 * sc; M02 = q02 * sc;
            M10 = q10 * sc; M11 = q11 * sc; M12 = q12 * sc;
            M20 = q20 * sc; M21 = q21 * sc; M22 = q22 * sc;
            e += eq + (float)ex;
        } else {
            M00 = q00; M01 = q01; M02 = q02;
            M10 = q10; M11 = q11; M12 = q12;
            M20 = q20; M21 = q21; M22 = q22;
            e += eq;
        }
        gold += gq;
    }

    if (lane == 0) {
        float* dst = sHalf[w];
        dst[0] = M00; dst[1] = M01; dst[2] = M02;
        dst[3] = M10; dst[4] = M11; dst[5] = M12;
        dst[6] = M20; dst[7] = M21; dst[8] = M22;
        dst[9] = e;   dst[10] = gold;
    }
    __syncthreads();

    // ---- per-row: alpha0 * H0 * H1, logZ, gold base term ----
    if (tid < RPB) {
        int rr = tid;
        const float* A  = sHalf[rr * 2];
        const float* Bm = sHalf[rr * 2 + 1];

        float4 e0 = emS[rr * EM_F4_PER_ROW];      // em[row][0][0..2]
        float a0 = __expf(e0.x), a1 = __expf(e0.y), a2 = __expf(e0.z);
        float u0 = fmaf(a2, A[6], fmaf(a1, A[3], a0 * A[0]));
        float u1 = fmaf(a2, A[7], fmaf(a1, A[4], a0 * A[1]));
        float u2 = fmaf(a2, A[8], fmaf(a1, A[5], a0 * A[2]));
        float v0 = fmaf(u2, Bm[6], fmaf(u1, Bm[3], u0 * Bm[0]));
        float v1 = fmaf(u2, Bm[7], fmaf(u1, Bm[4], u0 * Bm[1]));
        float v2 = fmaf(u2, Bm[8], fmaf(u1, Bm[5], u0 * Bm[2]));

        float esumT = A[9] + Bm[9];
        float goldT = A[10] + Bm[10];

        unsigned c0 = codesS[rr * 256];
        int   t0 = (int)(c0 & 3u);
        float m0 = (float)((c0 >> 2) & 1u);
        float em0t = (t0 == 0) ? e0.x : ((t0 == 1) ? e0.y : e0.z);
        goldT += m0 * em0t;

        float logZ = __logf(v0 + v1 + v2) + esumT * LN2F;
        srow[rr] = logZ - goldT;
    }
    __syncthreads();

    if (tid == 0) {
        g_partials[blockIdx.x] = (srow[0] + srow[1]) + (srow[2] + srow[3]);
        __threadfence();
        int tk = atomicAdd(&g_count, 1);
        sLast = (tk == NBLOCKS - 1);
    }
    __syncthreads();

    // ---- last block: fixed-order final reduction ----
    if (sLast) {
        float s = 0.f;
        #pragma unroll
        for (int i = 0; i < NBLOCKS / THREADS; ++i)
            s += __ldcg(&g_partials[tid * (NBLOCKS / THREADS) + i]);
        float* red = (float*)smem;                // reuse staging smem
        red[tid] = s;
        __syncthreads();
        #pragma unroll
        for (int st = THREADS / 2; st > 0; st >>= 1) {
            if (tid < st) red[tid] += red[tid + st];
            __syncthreads();
        }
        if (tid == 0) {
            out[0] = red[0] * (1.0f / (float)B_DIM);
            g_count = 0;                          // reset for next graph replay
        }
    }
}

extern "C" void kernel_launch(void* const* d_in, const int* in_sizes, int n_in,
                              void* d_out, int out_size)
{
    const float* emissions   = (const float*)d_in[0];
    const float* mask        = (const float*)d_in[1];
    const float* transitions = (const float*)d_in[2];
    const int*   tags        = (const int*)d_in[3];
    float* out = (float*)d_out;

    cudaFuncSetAttribute(crf_main_kernel,
                         cudaFuncAttributeMaxDynamicSharedMemorySize, SMEM_BYTES);
    crf_main_kernel<<<NBLOCKS, THREADS, SMEM_BYTES>>>(emissions, mask, transitions,
                                                      tags, out);
}